// round 17
// baseline (speedup 1.0000x reference)
#include <cuda_runtime.h>
#include <cuda_bf16.h>
#include <cooperative_groups.h>
#include <cstdint>
#include <cstddef>
#include <cstring>

namespace cg = cooperative_groups;

// Problem dims
#define Vv 32000
#define Ee 300
#define Hh 300
#define G4 1200   // 4*H
#define Bb 128
#define Tt 512
#define Oo 9
#define KP 320    // K padded (300 -> 320) for proj
#define KC 160    // KP/2 u32 cells per row (proj)

// ---------------- scratch (device globals: allocation-free rule) ----------------
__device__ float g_proj[2ull * Vv * G4];          // 307.2 MB
__device__ float g_h[2ull * Bb * Tt * Hh];        // 157.3 MB
// bf16 hi/lo splits (u32 = 2 packed bf16 along K)
__device__ unsigned g_emb_hi[(size_t)Vv * KC];
__device__ unsigned g_emb_lo[(size_t)Vv * KC];
__device__ unsigned g_wih_hi[2ull * G4 * KC];
__device__ unsigned g_wih_lo[2ull * G4 * KC];

typedef unsigned long long ull_t;

// ---------------- warp-level bf16 MMA (portable PTX, sm_80+) ----------------
__device__ __forceinline__ void mma16816(float* c, const unsigned* a, const unsigned* b) {
    asm volatile(
        "mma.sync.aligned.m16n8k16.row.col.f32.bf16.bf16.f32 "
        "{%0,%1,%2,%3}, {%4,%5,%6,%7}, {%8,%9}, {%0,%1,%2,%3};"
        : "+f"(c[0]), "+f"(c[1]), "+f"(c[2]), "+f"(c[3])
        : "r"(a[0]), "r"(a[1]), "r"(a[2]), "r"(a[3]), "r"(b[0]), "r"(b[1]));
}

__device__ __forceinline__ unsigned pack_bf16x2(float lo_val, float hi_val) {
    __nv_bfloat16 l = __float2bfloat16(lo_val);
    __nv_bfloat16 h = __float2bfloat16(hi_val);
    unsigned short a, b;
    memcpy(&a, &l, 2); memcpy(&b, &h, 2);
    return (unsigned)a | ((unsigned)b << 16);
}

// =================================================================
// K0: fp32 -> bf16 hi/lo split (K 300 -> 320 zero-pad)  [proj inputs]
// =================================================================
__global__ void split_kernel(const float* __restrict__ src,
                             unsigned* __restrict__ hi,
                             unsigned* __restrict__ lo,
                             int rows) {
    size_t idx = (size_t)blockIdx.x * blockDim.x + threadIdx.x;
    size_t total = (size_t)rows * KC;
    if (idx >= total) return;
    int row = (int)(idx / KC);
    int kc  = (int)(idx % KC);
    int k0 = kc * 2, k1 = kc * 2 + 1;
    float x0 = (k0 < Ee) ? src[(size_t)row * Ee + k0] : 0.f;
    float x1 = (k1 < Ee) ? src[(size_t)row * Ee + k1] : 0.f;
    __nv_bfloat16 h0 = __float2bfloat16(x0);
    __nv_bfloat16 h1 = __float2bfloat16(x1);
    __nv_bfloat16 l0 = __float2bfloat16(x0 - __bfloat162float(h0));
    __nv_bfloat16 l1 = __float2bfloat16(x1 - __bfloat162float(h1));
    unsigned uh, ul;
    {
        unsigned short a, b;
        memcpy(&a, &h0, 2); memcpy(&b, &h1, 2); uh = (unsigned)a | ((unsigned)b << 16);
        memcpy(&a, &l0, 2); memcpy(&b, &l1, 2); ul = (unsigned)a | ((unsigned)b << 16);
    }
    hi[idx] = uh;
    lo[idx] = ul;
}

// =================================================================
// K1: proj GEMM via mma.sync bf16, 3-term hi/lo split. (R12, unchanged)
// =================================================================
#define PJ_BM 128
#define PJ_BN 80
#define PJ_STR 20

__global__ void __launch_bounds__(256)
proj_mma_kernel(const float* __restrict__ bf,
                const float* __restrict__ bb) {
    __shared__ unsigned As_hi[PJ_BM * PJ_STR];
    __shared__ unsigned As_lo[PJ_BM * PJ_STR];
    __shared__ unsigned Bs_hi[PJ_BN * PJ_STR];
    __shared__ unsigned Bs_lo[PJ_BN * PJ_STR];

    const int tid  = threadIdx.x;
    const int wid  = tid >> 5;
    const int lane = tid & 31;
    const int wm   = wid & 3;
    const int wn   = wid >> 2;
    const int g    = lane >> 2;
    const int q    = lane & 3;

    const int n0  = blockIdx.x * PJ_BN;
    const int m0  = blockIdx.y * PJ_BM;
    const int dir = blockIdx.z;
    const float* __restrict__ bias = dir ? bb : bf;

    const unsigned* __restrict__ whi = g_wih_hi + (size_t)dir * G4 * KC;
    const unsigned* __restrict__ wlo = g_wih_lo + (size_t)dir * G4 * KC;

    float acc[2][5][4];
#pragma unroll
    for (int mt = 0; mt < 2; mt++)
#pragma unroll
        for (int nt = 0; nt < 5; nt++)
#pragma unroll
            for (int i = 0; i < 4; i++) acc[mt][nt][i] = 0.f;

    for (int kb = 0; kb < 10; kb++) {
#pragma unroll
        for (int it = 0; it < 2; it++) {
            int idx = tid + it * 256;
            int row = idx >> 2;
            int q4  = (idx & 3) * 4;
            size_t so = (size_t)(m0 + row) * KC + kb * 16 + q4;
            uint4 vh = *(const uint4*)(g_emb_hi + so);
            uint4 vl = *(const uint4*)(g_emb_lo + so);
            unsigned* dh = As_hi + row * PJ_STR + q4;
            unsigned* dl = As_lo + row * PJ_STR + q4;
            dh[0] = vh.x; dh[1] = vh.y; dh[2] = vh.z; dh[3] = vh.w;
            dl[0] = vl.x; dl[1] = vl.y; dl[2] = vl.z; dl[3] = vl.w;
        }
        if (tid < 160) {
#pragma unroll
            for (int it = 0; it < 2; it++) {
                int idx = tid + it * 160;
                int row = idx >> 2;
                int q4  = (idx & 3) * 4;
                size_t so = (size_t)(n0 + row) * KC + kb * 16 + q4;
                uint4 vh = *(const uint4*)(whi + so);
                uint4 vl = *(const uint4*)(wlo + so);
                unsigned* dh = Bs_hi + row * PJ_STR + q4;
                unsigned* dl = Bs_lo + row * PJ_STR + q4;
                dh[0] = vh.x; dh[1] = vh.y; dh[2] = vh.z; dh[3] = vh.w;
                dl[0] = vl.x; dl[1] = vl.y; dl[2] = vl.z; dl[3] = vl.w;
            }
        }
        __syncthreads();

#pragma unroll
        for (int sub = 0; sub < 2; sub++) {
            const int c0 = q + sub * 8;
            unsigned ah[2][4], al[2][4];
#pragma unroll
            for (int mt = 0; mt < 2; mt++) {
                int r = wm * 32 + mt * 16 + g;
                const unsigned* ph = As_hi + r * PJ_STR;
                const unsigned* pl = As_lo + r * PJ_STR;
                ah[mt][0] = ph[c0];
                ah[mt][1] = ph[8 * PJ_STR + c0];
                ah[mt][2] = ph[c0 + 4];
                ah[mt][3] = ph[8 * PJ_STR + c0 + 4];
                al[mt][0] = pl[c0];
                al[mt][1] = pl[8 * PJ_STR + c0];
                al[mt][2] = pl[c0 + 4];
                al[mt][3] = pl[8 * PJ_STR + c0 + 4];
            }
            unsigned bh[5][2], bl[5][2];
#pragma unroll
            for (int nt = 0; nt < 5; nt++) {
                int n = wn * 40 + nt * 8 + g;
                const unsigned* ph = Bs_hi + n * PJ_STR;
                const unsigned* pl = Bs_lo + n * PJ_STR;
                bh[nt][0] = ph[c0];  bh[nt][1] = ph[c0 + 4];
                bl[nt][0] = pl[c0];  bl[nt][1] = pl[c0 + 4];
            }
#pragma unroll
            for (int mt = 0; mt < 2; mt++)
#pragma unroll
                for (int nt = 0; nt < 5; nt++) {
                    mma16816(acc[mt][nt], ah[mt], bh[nt]);
                    mma16816(acc[mt][nt], ah[mt], bl[nt]);
                    mma16816(acc[mt][nt], al[mt], bh[nt]);
                }
        }
        __syncthreads();
    }

    float* cbase = g_proj + (size_t)dir * Vv * G4;
#pragma unroll
    for (int mt = 0; mt < 2; mt++) {
        int r = m0 + wm * 32 + mt * 16 + g;
#pragma unroll
        for (int nt = 0; nt < 5; nt++) {
            int n = n0 + wn * 40 + nt * 8 + q * 2;
            float b0v = bias[n], b1v = bias[n + 1];
            float2 v0 = make_float2(acc[mt][nt][0] + b0v, acc[mt][nt][1] + b1v);
            float2 v1 = make_float2(acc[mt][nt][2] + b0v, acc[mt][nt][3] + b1v);
            *(float2*)(cbase + (size_t)r * G4 + n) = v0;
            *(float2*)(cbase + (size_t)(r + 8) * G4 + n) = v1;
        }
    }
}

// =================================================================
// K2: BiLSTM recurrence, mma.sync bf16, TERM-PARALLEL (15 warps).
// Same as R16 plus the pad-rezero fix: the reduction scratch (placed in
// the dead hcur buffer) clobbers h pad cells (150/151 per row) that the
// W-alias MMA layout requires to be ZERO; each step we re-zero the pad
// cells of hnext after staging (64 words) so the invariant holds for
// our own buffer AND for rank 7's push source.
// =================================================================
#define REC_THREADS 480
#define W_STR   150
#define WHALF   24002
#define H_STR   152
#define HHALF   2432
#define HBUFW   4864
#define HBASE   (2 * WHALF)                 // 48004
#define REC_WORDS (2 * WHALF + 2 * HBUFW)   // 57732
#define REC_SMEM (REC_WORDS * 4)            // 230928 B

__device__ __forceinline__ void mbar_init_f(uint32_t addr, uint32_t count) {
    asm volatile("mbarrier.init.shared.b64 [%0], %1;" :: "r"(addr), "r"(count) : "memory");
}
__device__ __forceinline__ void mbar_arrive_rank(uint32_t local_mbar_addr, uint32_t rank) {
    asm volatile(
        "{\n\t"
        ".reg .b32 ra;\n\t"
        "mapa.shared::cluster.u32 ra, %0, %1;\n\t"
        "mbarrier.arrive.shared::cluster.b64 _, [ra];\n\t"
        "}"
        :: "r"(local_mbar_addr), "r"(rank) : "memory");
}
__device__ __forceinline__ void mbar_wait_parity_acq_cluster(uint32_t addr, uint32_t parity) {
    uint32_t done;
    asm volatile(
        "{\n\t"
        ".reg .pred p;\n\t"
        "mbarrier.try_wait.parity.acquire.cluster.shared::cta.b64 p, [%1], %2;\n\t"
        "selp.b32 %0, 1, 0, p;\n\t"
        "}"
        : "=r"(done) : "r"(addr), "r"(parity) : "memory");
    while (!done) {
        asm volatile(
            "{\n\t"
            ".reg .pred p;\n\t"
            "mbarrier.try_wait.parity.acquire.cluster.shared::cta.b64 p, [%1], %2, 0x989680;\n\t"
            "selp.b32 %0, 1, 0, p;\n\t"
            "}"
            : "=r"(done) : "r"(addr), "r"(parity) : "memory");
    }
}

__device__ __forceinline__ float sigmoidf_(float x) {
    return 1.0f / (1.0f + __expf(-x));
}
__device__ __forceinline__ float tanhf_(float x) {
    float xx = fminf(fmaxf(x, -15.f), 15.f);
    float e = __expf(-2.0f * xx);
    return (1.0f - e) / (1.0f + e);
}

__global__ void __cluster_dims__(8, 1, 1) __launch_bounds__(REC_THREADS, 1)
lstm_rec_kernel(const int* __restrict__ x,
                const float* __restrict__ Whh_f,
                const float* __restrict__ Whh_b) {
    extern __shared__ unsigned smu[];
    __shared__ unsigned long long mbars[2];

    cg::cluster_group cluster = cg::this_cluster();

    const int bx   = blockIdx.x;
    const int cid  = bx >> 3;           // 0..15
    const int rank = bx & 7;            // 0..7
    const int dir  = cid >> 3;          // 0,1
    const int bg   = cid & 7;           // 0..7
    const int b0   = bg * 16;
    const int h0   = rank * 40;
    const int h0c  = rank * 20;         // cell offset of own slice
    const int tid  = threadIdx.x;
    const int warp = tid >> 5;          // 0..14
    const int lane = tid & 31;
    const int term = warp / 5;          // 0..2
    const int oct  = warp % 5;          // 0..4 (j-oct)
    const int gg_  = lane >> 2;         // 0..7 (fragment row group)
    const int q    = lane & 3;          // 0..3

    const float* __restrict__ Whh = dir ? Whh_b : Whh_f;

    const uint32_t mbar_addr0 = (uint32_t)__cvta_generic_to_shared(&mbars[0]);
    const uint32_t mbar_addr1 = (uint32_t)__cvta_generic_to_shared(&mbars[1]);

    if (tid == 0) {
        mbar_init_f(mbar_addr0, 8);
        mbar_init_f(mbar_addr1, 8);
    }

    // ---- zero all SMEM (h buffers + W pads must be zero) ----
    for (int i = tid; i < REC_WORDS; i += REC_THREADS) smu[i] = 0u;
    __syncthreads();

    // ---- load + split W slice: row gi = gate*40 + jj, stride 150 cells ----
    if (tid < 160) {
        int gi = tid;                    // 0..159
        int gt = gi / 40;
        int jj = gi % 40;
        bool v = (h0 + jj) < Hh;
        const float* wrow = Whh + (size_t)(gt * Hh + (v ? (h0 + jj) : 0)) * Hh;
        unsigned* whi = smu + gi * W_STR;
        unsigned* wlo = smu + WHALF + gi * W_STR;
        for (int k4 = 0; k4 < Hh; k4 += 4) {
            float4 w = v ? *(const float4*)(wrow + k4) : make_float4(0.f, 0.f, 0.f, 0.f);
            int c = k4 >> 1;
            __nv_bfloat16 hx = __float2bfloat16(w.x), hy = __float2bfloat16(w.y);
            __nv_bfloat16 hz = __float2bfloat16(w.z), hw = __float2bfloat16(w.w);
            float lx = w.x - __bfloat162float(hx), ly = w.y - __bfloat162float(hy);
            float lz = w.z - __bfloat162float(hz), lw = w.w - __bfloat162float(hw);
            unsigned short s0, s1;
            memcpy(&s0, &hx, 2); memcpy(&s1, &hy, 2);
            whi[c]     = (unsigned)s0 | ((unsigned)s1 << 16);
            memcpy(&s0, &hz, 2); memcpy(&s1, &hw, 2);
            whi[c + 1] = (unsigned)s0 | ((unsigned)s1 << 16);
            wlo[c]     = pack_bf16x2(lx, ly);
            wlo[c + 1] = pack_bf16x2(lz, lw);
        }
    }
    __syncthreads();
    cluster.sync();   // barriers + zeroed buffers visible cluster-wide

    // batch rows for this thread's fragments
    const int rA = gg_;                  // fragment rows g, g+8
    const int rB = gg_ + 8;
    const int* xrA = x + (size_t)(b0 + rA) * Tt;
    const int* xrB = x + (size_t)(b0 + rB) * Tt;
    const float* ptab = g_proj + (size_t)dir * Vv * G4;

    // hidden cols for this thread (pair): jg, jg+1
    const int jl  = 8 * oct + 2 * q;     // 0..38 local
    const int jg  = h0 + jl;             // global even
    const int jgc = (jg <= 298) ? jg : 298;
    const bool jvalid = jg < Hh;         // jg <= 298 -> pair valid

    // W fragment base indices: row gi = gate*40 + 8*oct + g
    int wbase[4];
#pragma unroll
    for (int G = 0; G < 4; G++) wbase[G] = (G * 40 + 8 * oct + gg_) * W_STR + q;

    // A fragment offsets within an h half
    const int aoffA = rA * H_STR + q;
    const int aoffB = rB * H_STR + q;

    // staging cell for own hn pair (term0 threads)
    const int cellA = h0c + 4 * oct + q;
    const bool stage_ok = cellA < 150;

    // reduction scratch: zone in CURRENT h buffer, conflict-free layout:
    // word = hcur_base + oct*512 + lane + k*32   (k = 0..15)
    const unsigned red_off = (unsigned)(oct * 512 + lane);

    float cA0 = 0.f, cA1 = 0.f, cB0 = 0.f, cB1 = 0.f;
    uint32_t par0 = 0, par1 = 0;

    // ---- prologue: xp for step 0 (term0 only) ----
    float2 xpA[4], xpB[4];
    if (term == 0) {
        const int t0 = dir ? (Tt - 1) : 0;
        const float* pA = ptab + (size_t)xrA[t0] * G4;
        const float* pB = ptab + (size_t)xrB[t0] * G4;
#pragma unroll
        for (int G = 0; G < 4; G++) {
            xpA[G] = *(const float2*)(pA + G * Hh + jgc);
            xpB[G] = *(const float2*)(pB + G * Hh + jgc);
        }
    }

    for (int ti = 0; ti < Tt; ti++) {
        const int tcur = dir ? (Tt - 1 - ti) : ti;
        const int buf  = ti & 1;
        const unsigned hcur_base  = HBASE + buf * HBUFW;
        const unsigned hnext_base = HBASE + (buf ^ 1) * HBUFW;

        // ---- prefetch next xp (term0, before the wait) ----
        float2 xpnA[4], xpnB[4];
        if (term == 0) {
            const int tin = (ti + 1 < Tt) ? (ti + 1) : ti;
            const int tn  = dir ? (Tt - 1 - tin) : tin;
            const float* pA = ptab + (size_t)xrA[tn] * G4;
            const float* pB = ptab + (size_t)xrB[tn] * G4;
#pragma unroll
            for (int G = 0; G < 4; G++) {
                xpnA[G] = *(const float2*)(pA + G * Hh + jgc);
                xpnB[G] = *(const float2*)(pB + G * Hh + jgc);
            }
        }

        // ---- wait for h of step ti-1 ----
        if (ti > 0) {
            if (buf) { mbar_wait_parity_acq_cluster(mbar_addr1, par1); par1 ^= 1; }
            else     { mbar_wait_parity_acq_cluster(mbar_addr0, par0); par0 ^= 1; }
        }

        // ---- gate GEMM: this warp's single term over full K ----
        const unsigned* hh = smu + hcur_base;            // h hi half
        const unsigned* hl = smu + hcur_base + HHALF;    // h lo half
        const unsigned* Asrc = (term == 2) ? hl : hh;
        const unsigned* Bsrc = (term == 1) ? (smu + WHALF) : smu;

        float acc[4][4];
#pragma unroll
        for (int G = 0; G < 4; G++)
#pragma unroll
            for (int i = 0; i < 4; i++) acc[G][i] = 0.f;

#pragma unroll 1
        for (int kb = 0; kb < 19; kb++) {
            const int ko = kb * 8;
            unsigned a[4];
            a[0] = Asrc[aoffA + ko];     a[1] = Asrc[aoffB + ko];
            a[2] = Asrc[aoffA + ko + 4]; a[3] = Asrc[aoffB + ko + 4];
#pragma unroll
            for (int G = 0; G < 4; G++) {
                unsigned b[2];
                b[0] = Bsrc[wbase[G] + ko]; b[1] = Bsrc[wbase[G] + ko + 4];
                mma16816(acc[G], a, b);
            }
        }

        // ---- reduce term1/2 partials into term0 (scratch in hcur) ----
        __syncthreads();   // all hcur reads done; scratch area safe
        {
            unsigned* red = smu + hcur_base + red_off;
            if (term == 1) {
#pragma unroll
                for (int G = 0; G < 4; G++)
#pragma unroll
                    for (int i = 0; i < 4; i++)
                        red[(G * 4 + i) * 32] = __float_as_uint(acc[G][i]);
            }
            __syncthreads();
            if (term == 0) {
#pragma unroll
                for (int G = 0; G < 4; G++)
#pragma unroll
                    for (int i = 0; i < 4; i++)
                        acc[G][i] += __uint_as_float(red[(G * 4 + i) * 32]);
            }
            __syncthreads();
            if (term == 2) {
#pragma unroll
                for (int G = 0; G < 4; G++)
#pragma unroll
                    for (int i = 0; i < 4; i++)
                        red[(G * 4 + i) * 32] = __float_as_uint(acc[G][i]);
            }
            __syncthreads();
            if (term == 0) {
#pragma unroll
                for (int G = 0; G < 4; G++)
#pragma unroll
                    for (int i = 0; i < 4; i++)
                        acc[G][i] += __uint_as_float(red[(G * 4 + i) * 32]);
            }
        }

        // ---- LSTM cell update + staging (term0 only) ----
        float hnA0, hnA1, hnB0, hnB1;
        if (term == 0) {
            float i_, f_, g_, o_, tg;
            i_ = acc[0][0] + xpA[0].x; f_ = acc[1][0] + xpA[1].x;
            g_ = acc[2][0] + xpA[2].x; o_ = acc[3][0] + xpA[3].x;
            tg = tanhf_(g_); cA0 = sigmoidf_(f_) * cA0 + sigmoidf_(i_) * tg; hnA0 = sigmoidf_(o_) * tanhf_(cA0);
            i_ = acc[0][1] + xpA[0].y; f_ = acc[1][1] + xpA[1].y;
            g_ = acc[2][1] + xpA[2].y; o_ = acc[3][1] + xpA[3].y;
            tg = tanhf_(g_); cA1 = sigmoidf_(f_) * cA1 + sigmoidf_(i_) * tg; hnA1 = sigmoidf_(o_) * tanhf_(cA1);
            i_ = acc[0][2] + xpB[0].x; f_ = acc[1][2] + xpB[1].x;
            g_ = acc[2][2] + xpB[2].x; o_ = acc[3][2] + xpB[3].x;
            tg = tanhf_(g_); cB0 = sigmoidf_(f_) * cB0 + sigmoidf_(i_) * tg; hnB0 = sigmoidf_(o_) * tanhf_(cB0);
            i_ = acc[0][3] + xpB[0].y; f_ = acc[1][3] + xpB[1].y;
            g_ = acc[2][3] + xpB[2].y; o_ = acc[3][3] + xpB[3].y;
            tg = tanhf_(g_); cB1 = sigmoidf_(f_) * cB1 + sigmoidf_(i_) * tg; hnB1 = sigmoidf_(o_) * tanhf_(cB1);
        }

        if (ti + 1 < Tt) {
            // ---- stage hn (bf16 hi/lo) into NEXT buffer's own slice ----
            if (term == 0 && stage_ok) {
                __nv_bfloat16 hA0 = __float2bfloat16(hnA0), hA1 = __float2bfloat16(hnA1);
                __nv_bfloat16 hB0 = __float2bfloat16(hnB0), hB1 = __float2bfloat16(hnB1);
                unsigned short s0, s1;
                unsigned uA_hi, uB_hi;
                memcpy(&s0, &hA0, 2); memcpy(&s1, &hA1, 2); uA_hi = (unsigned)s0 | ((unsigned)s1 << 16);
                memcpy(&s0, &hB0, 2); memcpy(&s1, &hB1, 2); uB_hi = (unsigned)s0 | ((unsigned)s1 << 16);
                unsigned uA_lo = pack_bf16x2(hnA0 - __bfloat162float(hA0), hnA1 - __bfloat162float(hA1));
                unsigned uB_lo = pack_bf16x2(hnB0 - __bfloat162float(hB0), hnB1 - __bfloat162float(hB1));
                smu[hnext_base + rA * H_STR + cellA] = uA_hi;
                smu[hnext_base + rB * H_STR + cellA] = uB_hi;
                smu[hnext_base + HHALF + rA * H_STR + cellA] = uA_lo;
                smu[hnext_base + HHALF + rB * H_STR + cellA] = uB_lo;
            }
            // ---- re-zero pad cells (150,151) of hnext: the reduction
            // scratch corrupted them when this buffer served as hcur.
            // The W-alias MMA layout requires these to be ZERO, and rank
            // 7's push sources its own pads into peers' pads.
            if (tid < 64) {
                int prow = tid >> 2;              // 0..15
                int half = (tid >> 1) & 1;        // 0,1
                int pc   = 150 + (tid & 1);       // 150,151
                smu[hnext_base + half * HHALF + prow * H_STR + pc] = 0u;
            }
            __syncthreads();

            // ---- push own slice to 7 peers (1120 float4 jobs over 480 thr) ----
            for (int jj = tid; jj < 1120; jj += REC_THREADS) {
                const int slot = jj % 160;
                const int pr   = jj / 160 + 1;       // 1..7
                const int p_half = slot / 80;
                const int p_idx  = slot % 80;
                const int p_row  = p_idx / 5;
                const int p_ch   = p_idx % 5;
                if (rank == 7 && p_ch >= 3) continue;
                const unsigned w4 = hnext_base +
                    (unsigned)(p_half * HHALF + p_row * H_STR + h0c + p_ch * 4);
                float4 v = *(const float4*)(smu + w4);
                const int rrk = (rank + pr) & 7;
                unsigned* ph = (unsigned*)cluster.map_shared_rank(smu, rrk);
                *(float4*)(ph + w4) = v;
            }

            // ---- aggregated release-arrive on all 8 CTAs' barriers ----
            if (tid == 0) {
                asm volatile("fence.acq_rel.cluster;" ::: "memory");
                const uint32_t mb = buf ? mbar_addr0 : mbar_addr1;
#pragma unroll
                for (int rr = 0; rr < 8; rr++) mbar_arrive_rank(mb, rr);
            }
        }

        // ---- write h to global for the output stage (term0) ----
        if (term == 0 && jvalid) {
            size_t baseA = ((size_t)(dir * Bb + b0 + rA) * Tt + tcur) * Hh + jg;
            size_t baseB = ((size_t)(dir * Bb + b0 + rB) * Tt + tcur) * Hh + jg;
            *(float2*)(g_h + baseA) = make_float2(hnA0, hnA1);
            *(float2*)(g_h + baseB) = make_float2(hnB0, hnB1);
        }

        if (term == 0) {
#pragma unroll
            for (int G = 0; G < 4; G++) { xpA[G] = xpnA[G]; xpB[G] = xpnB[G]; }
        }
    }
}

// =================================================================
// K3: output linear + softmax. One warp per (b,t). (unchanged)
// =================================================================
__global__ void out_kernel(const float* __restrict__ W_lin,
                           const float* __restrict__ b_lin,
                           float* __restrict__ out) {
    const int warp = (blockIdx.x * blockDim.x + threadIdx.x) >> 5;
    const int lane = threadIdx.x & 31;
    if (warp >= Bb * Tt) return;
    const int b = warp / Tt;
    const int t = warp % Tt;

    const float* hf = g_h + ((size_t)(0 * Bb + b) * Tt + t) * Hh;
    const float* hb = g_h + ((size_t)(1 * Bb + b) * Tt + t) * Hh;

    float acc[Oo];
#pragma unroll
    for (int o = 0; o < Oo; o++) acc[o] = 0.f;

    for (int k = lane; k < Hh; k += 32) {
        float a = hf[k];
        float c = hb[k];
#pragma unroll
        for (int o = 0; o < Oo; o++)
            acc[o] += a * W_lin[o * (2 * Hh) + k] + c * W_lin[o * (2 * Hh) + Hh + k];
    }
#pragma unroll
    for (int o = 0; o < Oo; o++) {
#pragma unroll
        for (int off = 16; off > 0; off >>= 1)
            acc[o] += __shfl_xor_sync(0xFFFFFFFFu, acc[o], off);
        acc[o] += b_lin[o];
    }
    float mx = acc[0];
#pragma unroll
    for (int o = 1; o < Oo; o++) mx = fmaxf(mx, acc[o]);
    float s = 0.f;
    float e[Oo];
#pragma unroll
    for (int o = 0; o < Oo; o++) { e[o] = __expf(acc[o] - mx); s += e[o]; }
    float inv = 1.0f / s;
    if (lane < Oo) out[(size_t)warp * Oo + lane] = e[lane] * inv;
}

// =================================================================
// launcher
// =================================================================
extern "C" void kernel_launch(void* const* d_in, const int* in_sizes, int n_in,
                              void* d_out, int out_size) {
    const int*   x     = (const int*)  d_in[0];
    const float* emb   = (const float*)d_in[1];
    const float* Wih_f = (const float*)d_in[2];
    const float* Whh_f = (const float*)d_in[3];
    const float* b_f   = (const float*)d_in[4];
    const float* Wih_b = (const float*)d_in[5];
    const float* Whh_b = (const float*)d_in[6];
    const float* b_b   = (const float*)d_in[7];
    const float* W_lin = (const float*)d_in[8];
    const float* b_lin = (const float*)d_in[9];
    float* out = (float*)d_out;

    cudaFuncSetAttribute(lstm_rec_kernel,
                         cudaFuncAttributeMaxDynamicSharedMemorySize, REC_SMEM);

    static unsigned *p_emb_hi = nullptr, *p_emb_lo = nullptr, *p_wih_hi = nullptr, *p_wih_lo = nullptr;
    if (!p_emb_hi) {
        cudaGetSymbolAddress((void**)&p_emb_hi, g_emb_hi);
        cudaGetSymbolAddress((void**)&p_emb_lo, g_emb_lo);
        cudaGetSymbolAddress((void**)&p_wih_hi, g_wih_hi);
        cudaGetSymbolAddress((void**)&p_wih_lo, g_wih_lo);
    }

    // K0: hi/lo splits (proj inputs)
    {
        size_t cells = (size_t)Vv * KC;
        split_kernel<<<(unsigned)((cells + 255) / 256), 256>>>(emb, p_emb_hi, p_emb_lo, Vv);
        size_t wc = (size_t)G4 * KC;
        split_kernel<<<(unsigned)((wc + 255) / 256), 256>>>(Wih_f, p_wih_hi, p_wih_lo, G4);
        split_kernel<<<(unsigned)((wc + 255) / 256), 256>>>(Wih_b, p_wih_hi + wc, p_wih_lo + wc, G4);
    }

    // K1: proj via mma.sync bf16. grid = (15 n-tiles, 250 m-tiles, 2 dirs)
    {
        dim3 grid(G4 / PJ_BN, Vv / PJ_BM, 2);
        proj_mma_kernel<<<grid, 256>>>(b_f, b_b);
    }

    // K2: recurrence (term-parallel MMA). 128 CTAs, clusters of 8, 480 thr.
    lstm_rec_kernel<<<128, REC_THREADS, REC_SMEM>>>(x, Whh_f, Whh_b);

    // K3: output. 65536 warps.
    {
        int warps_per_block = 8;
        int blocks = (Bb * Tt) / warps_per_block;
        out_kernel<<<blocks, warps_per_block * 32>>>(W_lin, b_lin, out);
    }
}